// round 16
// baseline (speedup 1.0000x reference)
#include <cuda_runtime.h>
#include <math.h>
#include <stdint.h>

#define BSZ 1024
#define NN  100
#define HH  128
#define MTOT (BSZ * NN)   // 102400

// ---------------- scratch (no allocs allowed) ----------------
__device__ float g_h0[(size_t)MTOT * HH];
__device__ float g_tmp[(size_t)MTOT * 2 * HH];   // [A_in@h0 | A_out@h0]
__device__ float g_gi[(size_t)MTOT * 3 * HH];
__device__ float g_gh[(size_t)MTOT * 3 * HH];
__device__ float g_hid[(size_t)MTOT * HH];
__device__ float g_star[(size_t)BSZ * HH];
// tf32-rounded weights + derived
__device__ float g_wih[3 * HH * 2 * HH];
__device__ float g_whh[3 * HH * HH];
__device__ float g_we[2 * HH * HH];      // [W_ein | W_eout] rounded, adjacent
__device__ float g_whn[HH * 2 * HH];
__device__ float g_wc[3 * HH * 2 * HH];  // combined gi weight [384, 256]
__device__ float g_bc[3 * HH];           // combined gi bias
__device__ float g_zero[HH];

// ---------------- helpers ----------------
__device__ __forceinline__ float totf(float x) {
    uint32_t u; asm("cvt.rna.tf32.f32 %0, %1;" : "=r"(u) : "f"(x));
    return __uint_as_float(u);
}
__device__ __forceinline__ float sigm(float x) { return 1.f / (1.f + expf(-x)); }

__device__ __forceinline__ void mma8(float c[4], float2 a01, float2 a23, float2 b01) {
    asm volatile(
        "mma.sync.aligned.m16n8k8.row.col.f32.tf32.tf32.f32 "
        "{%0,%1,%2,%3},{%4,%5,%6,%7},{%8,%9},{%0,%1,%2,%3};"
        : "+f"(c[0]), "+f"(c[1]), "+f"(c[2]), "+f"(c[3])
        : "r"(__float_as_uint(a01.x)), "r"(__float_as_uint(a01.y)),
          "r"(__float_as_uint(a23.x)), "r"(__float_as_uint(a23.y)),
          "r"(__float_as_uint(b01.x)), "r"(__float_as_uint(b01.y)));
}

// ---------------- tensor-core tf32 GEMM (round-11 proven core) ----------------
// 256 thr, CTA tile 128x128, warp tile 32x64, BK=16, double buffer, 1 bar/K-step.
// float4-quad SMEM layout (see round-11 comments).
// EPI 0: plain store; 1: highway sigmoid blend; 2: tf32-rounded store.
// ADJ: blockIdx.z encodes (half, batch); A/C get half column offsets (B shared).
template<bool BT, bool GUARD, int EPI, bool SPLITK, bool RND, bool ADJ>
__global__ __launch_bounds__(256, 2)
void tc_gemm(const float* __restrict__ A1, const float* __restrict__ A2,
             long sA, int lda, int ksplit,
             const float* __restrict__ B1, const float* __restrict__ B2, int nsB,
             long sB, int ldb,
             const float* __restrict__ bias1, const float* __restrict__ bias2, int nsb,
             float* __restrict__ C, long sC, int ldc,
             int M, int N, int K)
{
    __shared__ float4 As4[2][8][66];
    __shared__ float4 Bs4[2][8][66];

    const long zsel = ADJ ? (long)(blockIdx.z & 1023) : (long)blockIdx.z;
    const int  half_adj = ADJ ? (int)(blockIdx.z >> 10) : 0;

    A1 += zsel * sA + (ADJ ? half_adj * NN : 0);
    C  += zsel * sC + (ADJ ? half_adj * HH : 0);

    const int m0 = blockIdx.y * 128, n0 = blockIdx.x * 128;
    const int tid = threadIdx.x;
    const int lane = tid & 31, warp = tid >> 5;
    const int wm = warp >> 1, wn = warp & 1;
    const int g = lane >> 2, tig = lane & 3;

    const int a_row = tid >> 1, a_kg = (tid & 1) << 3;
    const float* pA1 = A1 + (long)(m0 + a_row) * lda + a_kg;
    const float* pA2 = SPLITK ? (A2 + (long)(m0 + a_row) * lda + a_kg) : pA1;
    const int a_idx  = ((a_row >> 4) << 3) + (a_row & 7);
    const int a_half = (a_row >> 3) & 1;

    const float* Bp;
    int b_kg = 0, b_k = 0, b_n8 = 0;
    int bq = 0, bsel = 0;
    if (BT) {
        int b_n = tid >> 1; b_kg = (tid & 1) << 3;
        int gn = n0 + b_n;
        const float* Bsel = (gn < nsB) ? (B1 + (long)gn * ldb)
                                       : (B2 + (long)(gn - nsB) * ldb);
        Bp = Bsel + b_kg;
        int p = ((b_n >> 4) << 3) + (b_n & 7);
        bq = p ^ ((p >> 3) & 7);
        bsel = (b_n >> 3) & 1;
    } else {
        b_k = tid >> 4;
        b_n8 = (tid & 15) << 3;
        Bp = B1 + zsel * sB + (long)b_k * ldb + n0 + b_n8;
        bsel = (b_n8 >> 3) & 1;
    }

    float acc[2][8][4] = {};
    __align__(16) float va[8];
    __align__(16) float vb[8];
    const int T = (K + 15) >> 4;

    auto ldg = [&](int k0) {
        if (!GUARD) {
            const float* p;
            if (SPLITK) {
                int kk = k0 + a_kg;
                p = (kk < ksplit) ? (pA1 + k0) : (pA2 + (k0 - ksplit));
            } else {
                p = pA1 + k0;
            }
            *reinterpret_cast<float4*>(va)     = *reinterpret_cast<const float4*>(p);
            *reinterpret_cast<float4*>(va + 4) = *reinterpret_cast<const float4*>(p + 4);
        } else {
            bool rok = (m0 + a_row) < M;
            if (rok && (k0 + a_kg + 8) <= K) {
                *reinterpret_cast<float4*>(va)     = *reinterpret_cast<const float4*>(pA1 + k0);
                *reinterpret_cast<float4*>(va + 4) = *reinterpret_cast<const float4*>(pA1 + k0 + 4);
            } else {
                #pragma unroll
                for (int j = 0; j < 8; j++)
                    va[j] = (rok && (k0 + a_kg + j) < K) ? pA1[k0 + j] : 0.f;
            }
        }
        if (BT) {
            *reinterpret_cast<float4*>(vb)     = *reinterpret_cast<const float4*>(Bp + k0);
            *reinterpret_cast<float4*>(vb + 4) = *reinterpret_cast<const float4*>(Bp + k0 + 4);
        } else {
            if ((k0 + b_k) < K) {
                const float* bp = Bp + (long)k0 * ldb;
                *reinterpret_cast<float4*>(vb)     = *reinterpret_cast<const float4*>(bp);
                *reinterpret_cast<float4*>(vb + 4) = *reinterpret_cast<const float4*>(bp + 4);
            } else {
                #pragma unroll
                for (int j = 0; j < 8; j++) vb[j] = 0.f;
            }
        }
    };

    auto sts = [&](int s) {
        #pragma unroll
        for (int j = 0; j < 8; j++) {
            int k = a_kg + j;
            int srow = ((k >> 3) << 2) + (k & 3);
            int comp = (((k >> 2) & 1) << 1) | a_half;
            (&As4[s][srow][a_idx].x)[comp] = RND ? totf(va[j]) : va[j];
        }
        if (BT) {
            #pragma unroll
            for (int j = 0; j < 8; j++) {
                int k = b_kg + j;
                int srow = ((k >> 3) << 2) + (k & 3);
                int comp = (bsel << 1) | ((k >> 2) & 1);
                (&Bs4[s][srow][bq].x)[comp] = RND ? totf(vb[j]) : vb[j];
            }
        } else {
            int srow = ((b_k >> 3) << 2) + (b_k & 3);
            int comp = (bsel << 1) | ((b_k >> 2) & 1);
            int p0 = (b_n8 >> 4) << 3;
            int x  = (p0 >> 3) & 7;
            #pragma unroll
            for (int j = 0; j < 8; j++) {
                int q = p0 + (j ^ x);
                (&Bs4[s][srow][q].x)[comp] = RND ? totf(vb[j]) : vb[j];
            }
        }
    };

    auto comp = [&](int s) {
        #pragma unroll
        for (int ks = 0; ks < 2; ks++) {
            float4 af[2], bf[4];
            #pragma unroll
            for (int mt = 0; mt < 2; mt++)
                af[mt] = As4[s][ks * 4 + tig][(wm * 2 + mt) * 8 + g];
            #pragma unroll
            for (int np = 0; np < 4; np++) {
                int j = wn * 32 + np * 8 + g;
                bf[np] = Bs4[s][ks * 4 + tig][j ^ ((j >> 3) & 7)];
            }
            #pragma unroll
            for (int mt = 0; mt < 2; mt++)
                #pragma unroll
                for (int np = 0; np < 4; np++) {
                    mma8(acc[mt][2 * np],
                         make_float2(af[mt].x, af[mt].y), make_float2(af[mt].z, af[mt].w),
                         make_float2(bf[np].x, bf[np].y));
                    mma8(acc[mt][2 * np + 1],
                         make_float2(af[mt].x, af[mt].y), make_float2(af[mt].z, af[mt].w),
                         make_float2(bf[np].z, bf[np].w));
                }
        }
    };

    ldg(0); sts(0); __syncthreads();
    for (int t = 0; t < T; t++) {
        if (t + 1 < T) ldg((t + 1) << 4);
        comp(t & 1);
        if (t + 1 < T) { sts((t + 1) & 1); __syncthreads(); }
    }

    // ---------------- epilogue ----------------
    #pragma unroll
    for (int mt = 0; mt < 2; mt++) {
        int mrow = m0 + wm * 32 + mt * 16 + g;
        #pragma unroll
        for (int half = 0; half < 2; half++) {
            int m = mrow + half * 8;
            if (GUARD && m >= M) continue;
            #pragma unroll
            for (int nt = 0; nt < 8; nt++) {
                int n = n0 + wn * 64 + nt * 8 + tig * 2;
                float bv0 = (n     < nsb) ? bias1[n]     : bias2[n - nsb];
                float bv1 = (n + 1 < nsb) ? bias1[n + 1] : bias2[n + 1 - nsb];
                float v0 = acc[mt][nt][half * 2 + 0] + bv0;
                float v1 = acc[mt][nt][half * 2 + 1] + bv1;
                float2* cp = reinterpret_cast<float2*>(C + (long)m * ldc + n);
                if (EPI == 1) {
                    float2 hv = *reinterpret_cast<const float2*>(A1 + (long)m * lda + n);
                    float2 dv = *reinterpret_cast<const float2*>(A2 + (long)m * lda + n);
                    float a0 = sigm(v0), a1 = sigm(v1);
                    *cp = make_float2(a0 * hv.x + (1.f - a0) * dv.x,
                                      a1 * hv.y + (1.f - a1) * dv.y);
                } else if (EPI == 2) {
                    *cp = make_float2(totf(v0), totf(v1));
                } else {
                    *cp = make_float2(v0, v1);
                }
            }
        }
    }
}

// ---------------- fused weight rounding + zero (single launch) ----------------
__global__ void wround_k(const float4* w_ih, const float4* w_hh,
                         const float4* W_ein, const float4* W_eout, const float4* W_hn,
                         float4* wih, float4* whh, float4* we, float4* whn,
                         float4* zero)
{
    const int S0 = 24576, S1 = S0 + 12288, S2 = S1 + 4096, S3 = S2 + 4096,
              S4 = S3 + 8192, S5 = S4 + 32;
    for (int i = blockIdx.x * blockDim.x + threadIdx.x; i < S5; i += gridDim.x * blockDim.x) {
        if (i >= S4) { zero[i - S4] = make_float4(0.f, 0.f, 0.f, 0.f); continue; }
        const float4* s; float4* d; int j;
        if      (i < S0) { s = w_ih;   d = wih;        j = i; }
        else if (i < S1) { s = w_hh;   d = whh;        j = i - S0; }
        else if (i < S2) { s = W_ein;  d = we;         j = i - S1; }
        else if (i < S3) { s = W_eout; d = we + 4096;  j = i - S2; }
        else             { s = W_hn;   d = whn;        j = i - S3; }
        float4 v = s[j];
        d[j] = make_float4(totf(v.x), totf(v.y), totf(v.z), totf(v.w));
    }
}

// ---------------- combined gi bias: bc = b_ih + [b_iah|b_oah] @ w_ih^T ----------
__global__ void bc_k(const float* __restrict__ b_ih,
                     const float* __restrict__ b_iah, const float* __restrict__ b_oah,
                     const float* __restrict__ w_ih_raw, float* __restrict__ bc)
{
    int gidx = blockIdx.x * blockDim.x + threadIdx.x;
    if (gidx >= 3 * HH) return;
    float s = b_ih[gidx];
    const float* wr = w_ih_raw + (long)gidx * 2 * HH;
    #pragma unroll 4
    for (int c = 0; c < HH; c++) s += b_iah[c] * wr[c];
    #pragma unroll 4
    for (int c = 0; c < HH; c++) s += b_oah[c] * wr[HH + c];
    bc[gidx] = s;
}

// ---------------- wide gather (rounded) ----------------
__global__ void gather_k(const int* __restrict__ inputs,
                         const float4* __restrict__ emb4,
                         float4* __restrict__ h04, long total4)
{
    long i = (long)blockIdx.x * blockDim.x + threadIdx.x;
    if (i >= total4) return;
    long m = i >> 5;
    int  t = (int)(i & 31);
    float4 v = emb4[(long)inputs[m] * 32 + t];
    h04[i] = make_float4(totf(v.x), totf(v.y), totf(v.z), totf(v.w));
}

__global__ void pool_k(const float* __restrict__ h0,
                       const int* __restrict__ gm,
                       float* __restrict__ star)
{
    int b = blockIdx.x, t = threadIdx.x;
    const float* hb = h0 + (long)b * NN * HH;
    const int* gb = gm + b * NN;
    float s0 = 0.f, s1 = 0.f, s2 = 0.f, s3 = 0.f, c = 0.f;
    #pragma unroll 1
    for (int i = 0; i < NN; i += 4) {
        float g0 = (float)gb[i],     g1 = (float)gb[i + 1];
        float g2 = (float)gb[i + 2], g3 = (float)gb[i + 3];
        s0 += g0 * hb[(long)(i    ) * HH + t];
        s1 += g1 * hb[(long)(i + 1) * HH + t];
        s2 += g2 * hb[(long)(i + 2) * HH + t];
        s3 += g3 * hb[(long)(i + 3) * HH + t];
        c += g0 + g1 + g2 + g3;
    }
    star[b * HH + t] = (s0 + s1 + s2 + s3) / c;
}

// ---------------- wide GRU elementwise (float4) ----------------
__global__ void gru_k(const float4* __restrict__ gi4, const float4* __restrict__ gh4,
                      const float4* __restrict__ h04, float4* __restrict__ hout4,
                      long total4)
{
    long i = (long)blockIdx.x * blockDim.x + threadIdx.x;
    if (i >= total4) return;
    long m = i >> 5;
    int  j = (int)(i & 31);
    long base = m * 96;
    float4 ir = gi4[base + j], ii = gi4[base + 32 + j], in_ = gi4[base + 64 + j];
    float4 hr = gh4[base + j], hi = gh4[base + 32 + j], hn  = gh4[base + 64 + j];
    float4 h  = h04[i];
    float4 o;
    { float r = sigm(ir.x + hr.x); float ig = sigm(ii.x + hi.x);
      float ng = tanhf(in_.x + r * hn.x); o.x = ng + ig * (h.x - ng); }
    { float r = sigm(ir.y + hr.y); float ig = sigm(ii.y + hi.y);
      float ng = tanhf(in_.y + r * hn.y); o.y = ng + ig * (h.y - ng); }
    { float r = sigm(ir.z + hr.z); float ig = sigm(ii.z + hi.z);
      float ng = tanhf(in_.z + r * hn.z); o.z = ng + ig * (h.z - ng); }
    { float r = sigm(ir.w + hr.w); float ig = sigm(ii.w + hi.w);
      float ng = tanhf(in_.w + r * hn.w); o.w = ng + ig * (h.w - ng); }
    hout4[i] = o;
}

// ---------------- star blend + attention pooling ----------------
__global__ void star_k(float* __restrict__ hidden,
                       const int* __restrict__ gm,
                       const float* __restrict__ star_in,
                       float* __restrict__ star_out)
{
    const float inv_sqrt_h = 0.0883883476483184f;
    int b = blockIdx.x;
    int t = threadIdx.x;
    int lane = t & 31, warp = t >> 5;

    __shared__ float st[HH];
    __shared__ float w[NN];
    __shared__ float red[HH];

    st[t] = star_in[(long)b * HH + t];
    __syncthreads();

    float ssp = 0.f;
    #pragma unroll
    for (int u = 0; u < 4; u++) { float v = st[lane + 32 * u]; ssp += v * v; }
    #pragma unroll
    for (int off = 16; off > 0; off >>= 1) ssp += __shfl_xor_sync(0xffffffffu, ssp, off);
    float ss = ssp;

    float* hb = hidden + (long)b * NN * HH;

    for (int i = warp; i < NN; i += 4) {
        float* hr = hb + (long)i * HH;
        float d = 0.f;
        #pragma unroll
        for (int u = 0; u < 4; u++) d += hr[lane + 32 * u] * st[lane + 32 * u];
        #pragma unroll
        for (int off = 16; off > 0; off >>= 1) d += __shfl_xor_sync(0xffffffffu, d, off);
        float alpha = sigm(d * inv_sqrt_h);
        #pragma unroll
        for (int u = 0; u < 4; u++) {
            int c = lane + 32 * u;
            hr[c] = totf((1.f - alpha) * hr[c] + alpha * st[c]);
        }
        float d2 = (1.f - alpha) * d + alpha * ss;
        if (lane == 0) w[i] = expf(d2) * (float)gm[b * NN + i];
    }
    __syncthreads();

    red[t] = (t < NN) ? w[t] : 0.f;
    __syncthreads();
    for (int s = 64; s > 0; s >>= 1) {
        if (t < s) red[t] += red[t + s];
        __syncthreads();
    }
    float S = red[0] + 1e-24f;

    float a0 = 0.f, a1 = 0.f, a2 = 0.f, a3 = 0.f;
    #pragma unroll 1
    for (int i = 0; i < NN; i += 4) {
        a0 += w[i]     * hb[(long)(i    ) * HH + t];
        a1 += w[i + 1] * hb[(long)(i + 1) * HH + t];
        a2 += w[i + 2] * hb[(long)(i + 2) * HH + t];
        a3 += w[i + 3] * hb[(long)(i + 3) * HH + t];
    }
    star_out[(long)b * HH + t] = (a0 + a1 + a2 + a3) / S;
}

// ---------------- launch ----------------
extern "C" void kernel_launch(void* const* d_in, const int* in_sizes, int n_in,
                              void* d_out, int out_size)
{
    const int*   inputs = (const int*)d_in[0];
    const float* A      = (const float*)d_in[1];
    const int*   gm     = (const int*)d_in[2];
    const float* emb    = (const float*)d_in[3];
    const float* w_ih   = (const float*)d_in[4];
    const float* w_hh   = (const float*)d_in[5];
    const float* b_ih   = (const float*)d_in[6];
    const float* b_hh   = (const float*)d_in[7];
    const float* b_iah  = (const float*)d_in[8];
    const float* b_oah  = (const float*)d_in[9];
    const float* W_ein  = (const float*)d_in[10];
    const float* b_ein  = (const float*)d_in[11];
    const float* W_eout = (const float*)d_in[12];
    const float* b_eout = (const float*)d_in[13];
    const float* W_hn   = (const float*)d_in[14];
    const float* b_hn   = (const float*)d_in[15];
    float* out = (float*)d_out;
    (void)b_ein; (void)b_eout;   // folded into bc via reassociation? no — b_ein/b_eout:
    // NOTE: e_in = h0@W_ein^T + b_ein; input_in = A_in@e_in + b_iah.
    // A_in@b_ein term: input_in[m,c] += (sum_j A_in[m,j]) * b_ein[c]  — NOT constant!
    // => must keep b_ein/b_eout: handled below via rowsum trick.

    float *h0, *tmp, *gi, *gh, *hid, *star;
    float *wih, *whh, *we, *whn, *wc, *bc, *zero;
    cudaGetSymbolAddress((void**)&h0,   g_h0);
    cudaGetSymbolAddress((void**)&tmp,  g_tmp);
    cudaGetSymbolAddress((void**)&gi,   g_gi);
    cudaGetSymbolAddress((void**)&gh,   g_gh);
    cudaGetSymbolAddress((void**)&hid,  g_hid);
    cudaGetSymbolAddress((void**)&star, g_star);
    cudaGetSymbolAddress((void**)&wih,  g_wih);
    cudaGetSymbolAddress((void**)&whh,  g_whh);
    cudaGetSymbolAddress((void**)&we,   g_we);
    cudaGetSymbolAddress((void**)&whn,  g_whn);
    cudaGetSymbolAddress((void**)&wc,   g_wc);
    cudaGetSymbolAddress((void**)&bc,   g_bc);
    cudaGetSymbolAddress((void**)&zero, g_zero);

    const long totBNH = (long)MTOT * HH;
    const int BIG = 1 << 30;

    // 0) round weights + zeros (one launch); combined bias bc
    wround_k<<<208, 256>>>((const float4*)w_ih, (const float4*)w_hh,
                           (const float4*)W_ein, (const float4*)W_eout, (const float4*)W_hn,
                           (float4*)wih, (float4*)whh, (float4*)we, (float4*)whn,
                           (float4*)zero);
    bc_k<<<3, 128>>>(b_ih, b_iah, b_oah, w_ih, bc);

    // 0b) Wc[:, z*128:(z+1)*128] = wih[:, z*128:] @ We_z   (z=0: W_ein, z=1: W_eout)
    //     tiny non-BT GEMM, grid (1, 3, 2); rounds output (EPI=2)
    tc_gemm<false, false, 2, false, false, false><<<dim3(1, 3, 2), 256>>>(
        wih, wih, 128, 2 * HH, 0,
        we, we, BIG, (long)HH * HH, HH,
        zero, zero, BIG,
        wc, 128, 2 * HH,
        3 * HH, HH, HH);

    // 1) wide gather (rounded) + initial star
    gather_k<<<(unsigned)((totBNH / 4 + 255) / 256), 256>>>(
        inputs, (const float4*)emb, (float4*)h0, totBNH / 4);
    pool_k<<<BSZ, HH>>>(h0, gm, star);

    // 2) adjacency: tmp = [A_in@h0 + 1*b_ein_rowsum? ...]
    //    e bias handling: input_in = A_in@(h0@W_ein^T) + A_in@1*b_ein^T + b_iah.
    //    The A@1*b^T term: gi contribution = rs_in[m] * (b_ein@Wih_in^T)[g] — handled
    //    by augmenting tmp with NOTHING here; instead we append the b_e terms through
    //    Wc by adding one extra K... -> simplest exact route: fold b_ein into h0 is
    //    impossible; so keep b_e effect via tmp bias = rowsum * b_e projected.
    //    We implement exactly: tmp = A_half @ h0   (bias zero),
    //    and gi gains term rs[m,half] * q_half[g], where q_half = b_e @ We-side of wih?
    //    NO — q_half[g] = sum_c b_e[c] * wih[g, half*128 + c]. rs[m,half]=sum_j A_half[m,j].
    //    We fold this by writing rs into tmp as... K would grow. Instead compute in gru:
    //    too invasive. EXACT alternative: append b_e to the Wc pipeline by adding the
    //    b_e@wih projection scaled by rowsum in a tiny elementwise pass on gi.
    tc_gemm<false, true, 2, false, true, true><<<dim3(1, 1, 2 * BSZ), 256>>>(
        A, A, (long)NN * 2 * NN, 2 * NN, 0,
        h0, h0, BIG, (long)NN * HH, HH,
        zero, zero, BIG,
        tmp, (long)NN * 2 * HH, 2 * HH,
        NN, HH, NN);

    // 2b) rowsum-based b_ein/b_eout correction folded into gi AFTER the big GEMM:
    //     gi[m,g] += rs_in[m]*qin[g] + rs_out[m]*qout[g]
    //     Implemented by augmenting tmp columns? Keep it exact & simple:
    //     compute per-row sums of A halves into tmp's spare precision path is not
    //     available; instead do it in a fused pass below (rsfix_k) before gru.

    // 3) gi = tmp @ Wc^T + bc   (K=256)
    tc_gemm<true, false, 0, false, false, false><<<dim3(3, MTOT / 128), 256>>>(
        tmp, tmp, 0, 2 * HH, 0,
        wc, wc, BIG, 0, 2 * HH,
        bc, bc, BIG,
        gi, 0, 3 * HH,
        MTOT, 3 * HH, 2 * HH);

    // 3b) exact b_ein/b_eout correction:
    //     gi[m,g] += rs_in[m] * (b_ein @ wih[:, :128]^T)[g] + rs_out[m] * (b_eout @ wih[:,128:]^T)[g]
    {
        // q vectors into g_bc+384? use dedicated lambda kernel below
    }
    // rsfix kernel: computes row sums of A halves and adds correction to gi
    {
        struct L {};
    }
    extern __global__ void rsfix_k(const float*, const float*, const float*,
                                   const float*, const float*, float*);
    rsfix_k<<<dim3(3, MTOT / 128), 256>>>(A, b_ein, b_eout, w_ih, nullptr, gi);

    // 4) gh = h0 @ w_hh^T + b_hh
    tc_gemm<true, false, 0, false, false, false><<<dim3(3, MTOT / 128), 256>>>(
        h0, h0, 0, HH, 0,
        whh, whh, BIG, 0, HH,
        b_hh, b_hh, BIG,
        gh, 0, 3 * HH,
        MTOT, 3 * HH, HH);

    // 5) GRU -> hid
    gru_k<<<(unsigned)((totBNH / 4 + 255) / 256), 256>>>(
        (const float4*)gi, (const float4*)gh, (const float4*)h0,
        (float4*)hid, totBNH / 4);

    // 6) star blend + attention pooling
    star_k<<<BSZ, HH>>>(hid, gm, star, out + totBNH);

    // 7) highway fused
    tc_gemm<true, false, 1, true, false, false><<<dim3(1, MTOT / 128), 256>>>(
        h0, hid, 0, HH, HH,
        whn, whn, BIG, 0, 2 * HH,
        b_hn, b_hn, BIG,
        out, 0, HH,
        MTOT, HH, 2 * HH);
}

// gi[m,g] += rs_in[m]*qin[g] + rs_out[m]*qout[g]
// qin[g] = sum_c b_ein[c]*w_ih[g,c]; qout[g] = sum_c b_eout[c]*w_ih[g,128+c]
// blockIdx.x selects gate block (128 g's), blockIdx.y selects 128 m's.
__global__ void rsfix_k(const float* __restrict__ A,
                        const float* __restrict__ b_ein, const float* __restrict__ b_eout,
                        const float* __restrict__ w_ih_raw, const float* __restrict__ unused,
                        float* __restrict__ gi)
{
    __shared__ float q[128];        // q for this gate block: qin+? both needed
    __shared__ float qo[128];
    __shared__ float rs[128][2];    // rowsums for 128 rows
    int tid = threadIdx.x;          // 256 threads
    int g0 = blockIdx.x * 128;
    long m0 = (long)blockIdx.y * 128;

    // q vectors (2 per g): 128 g's, threads 0-127 do qin, 128-255 qout
    {
        int gg = g0 + (tid & 127);
        const float* wr = w_ih_raw + (long)gg * 256;
        float s = 0.f;
        if (tid < 128) { for (int c = 0; c < 128; c++) s += b_ein[c]  * wr[c];       q[tid & 127] = s; }
        else           { for (int c = 0; c < 128; c++) s += b_eout[c] * wr[128 + c]; qo[tid & 127] = s; }
    }
    // rowsums: 128 rows, 2 halves; thread pairs
    {
        int r = tid >> 1, hf = tid & 1;
        long m = m0 + r;
        long b = m / NN, i = m % NN;
        const float* ar = A + b * NN * 2 * NN + i * 2 * NN + hf * NN;
        float s = 0.f;
        for (int j = 0; j < NN; j++) s += ar[j];
        rs[r][hf] = s;
    }
    __syncthreads();

    // apply: each thread covers 128*128/256 = 64 (m,g) pairs
    for (int u = tid; u < 128 * 128; u += 256) {
        int r = u >> 7, gg = u & 127;
        long m = m0 + r;
        gi[m * 384 + g0 + gg] += rs[r][0] * q[gg] + rs[r][1] * qo[gg];
    }
}

// round 17
// speedup vs baseline: 1.5842x; 1.5842x over previous
#include <cuda_runtime.h>
#include <math.h>
#include <stdint.h>

#define BSZ 1024
#define NN  100
#define HH  128
#define MTOT (BSZ * NN)   // 102400

// ---------------- scratch (no allocs allowed) ----------------
__device__ float g_h0[(size_t)MTOT * HH];
__device__ float g_tmp[(size_t)MTOT * 2 * HH];   // [A_in@h0 | A_out@h0]
__device__ float g_gi[(size_t)MTOT * 3 * HH];
__device__ float g_gh[(size_t)MTOT * 3 * HH];
__device__ float g_hid[(size_t)MTOT * HH];
__device__ float g_star[(size_t)BSZ * HH];
__device__ float g_rs[(size_t)MTOT * 2];         // A rowsums per half
// tf32-rounded weights + derived
__device__ float g_wih[3 * HH * 2 * HH];
__device__ float g_whh[3 * HH * HH];
__device__ float g_we[2 * HH * HH];      // [W_ein | W_eout] rounded, adjacent
__device__ float g_whn[HH * 2 * HH];
__device__ float g_wc[3 * HH * 2 * HH];  // combined gi weight [384, 256]
__device__ float g_bc[3 * HH];           // combined gi bias
__device__ float g_qv[2 * 3 * HH];       // [qin(384) | qout(384)]
__device__ float g_zero[HH];

// ---------------- helpers ----------------
__device__ __forceinline__ float totf(float x) {
    uint32_t u; asm("cvt.rna.tf32.f32 %0, %1;" : "=r"(u) : "f"(x));
    return __uint_as_float(u);
}
__device__ __forceinline__ float sigm(float x) { return 1.f / (1.f + expf(-x)); }

__device__ __forceinline__ void mma8(float c[4], float2 a01, float2 a23, float2 b01) {
    asm volatile(
        "mma.sync.aligned.m16n8k8.row.col.f32.tf32.tf32.f32 "
        "{%0,%1,%2,%3},{%4,%5,%6,%7},{%8,%9},{%0,%1,%2,%3};"
        : "+f"(c[0]), "+f"(c[1]), "+f"(c[2]), "+f"(c[3])
        : "r"(__float_as_uint(a01.x)), "r"(__float_as_uint(a01.y)),
          "r"(__float_as_uint(a23.x)), "r"(__float_as_uint(a23.y)),
          "r"(__float_as_uint(b01.x)), "r"(__float_as_uint(b01.y)));
}

// ---------------- tensor-core tf32 GEMM (round-11 proven core) ----------------
// 256 thr, CTA tile 128x128, warp tile 32x64, BK=16, double buffer, 1 bar/K-step.
// EPI 0: plain store; 1: highway sigmoid blend; 2: tf32-rounded store.
// ADJ: blockIdx.z encodes (half, batch); A/C get half offsets (B shared h0 block).
template<bool BT, bool GUARD, int EPI, bool SPLITK, bool RND, bool ADJ>
__global__ __launch_bounds__(256, 2)
void tc_gemm(const float* __restrict__ A1, const float* __restrict__ A2,
             long sA, int lda, int ksplit,
             const float* __restrict__ B1, const float* __restrict__ B2, int nsB,
             long sB, int ldb,
             const float* __restrict__ bias1, const float* __restrict__ bias2, int nsb,
             float* __restrict__ C, long sC, int ldc,
             int M, int N, int K)
{
    __shared__ float4 As4[2][8][66];
    __shared__ float4 Bs4[2][8][66];

    const long zsel = ADJ ? (long)(blockIdx.z & 1023) : (long)blockIdx.z;
    const int  half_adj = ADJ ? (int)(blockIdx.z >> 10) : 0;

    A1 += zsel * sA + (ADJ ? half_adj * NN : 0);
    C  += zsel * sC + (ADJ ? half_adj * HH : 0);

    const int m0 = blockIdx.y * 128, n0 = blockIdx.x * 128;
    const int tid = threadIdx.x;
    const int lane = tid & 31, warp = tid >> 5;
    const int wm = warp >> 1, wn = warp & 1;
    const int g = lane >> 2, tig = lane & 3;

    const int a_row = tid >> 1, a_kg = (tid & 1) << 3;
    const float* pA1 = A1 + (long)(m0 + a_row) * lda + a_kg;
    const float* pA2 = SPLITK ? (A2 + (long)(m0 + a_row) * lda + a_kg) : pA1;
    const int a_idx  = ((a_row >> 4) << 3) + (a_row & 7);
    const int a_half = (a_row >> 3) & 1;

    const float* Bp;
    int b_kg = 0, b_k = 0, b_n8 = 0;
    int bq = 0, bsel = 0;
    if (BT) {
        int b_n = tid >> 1; b_kg = (tid & 1) << 3;
        int gn = n0 + b_n;
        const float* Bsel = (gn < nsB) ? (B1 + (long)gn * ldb)
                                       : (B2 + (long)(gn - nsB) * ldb);
        Bp = Bsel + b_kg;
        int p = ((b_n >> 4) << 3) + (b_n & 7);
        bq = p ^ ((p >> 3) & 7);
        bsel = (b_n >> 3) & 1;
    } else {
        b_k = tid >> 4;
        b_n8 = (tid & 15) << 3;
        Bp = B1 + zsel * sB + (long)b_k * ldb + n0 + b_n8;
        bsel = (b_n8 >> 3) & 1;
    }

    float acc[2][8][4] = {};
    __align__(16) float va[8];
    __align__(16) float vb[8];
    const int T = (K + 15) >> 4;

    auto ldg = [&](int k0) {
        if (!GUARD) {
            const float* p;
            if (SPLITK) {
                int kk = k0 + a_kg;
                p = (kk < ksplit) ? (pA1 + k0) : (pA2 + (k0 - ksplit));
            } else {
                p = pA1 + k0;
            }
            *reinterpret_cast<float4*>(va)     = *reinterpret_cast<const float4*>(p);
            *reinterpret_cast<float4*>(va + 4) = *reinterpret_cast<const float4*>(p + 4);
        } else {
            bool rok = (m0 + a_row) < M;
            if (rok && (k0 + a_kg + 8) <= K) {
                *reinterpret_cast<float4*>(va)     = *reinterpret_cast<const float4*>(pA1 + k0);
                *reinterpret_cast<float4*>(va + 4) = *reinterpret_cast<const float4*>(pA1 + k0 + 4);
            } else {
                #pragma unroll
                for (int j = 0; j < 8; j++)
                    va[j] = (rok && (k0 + a_kg + j) < K) ? pA1[k0 + j] : 0.f;
            }
        }
        if (BT) {
            *reinterpret_cast<float4*>(vb)     = *reinterpret_cast<const float4*>(Bp + k0);
            *reinterpret_cast<float4*>(vb + 4) = *reinterpret_cast<const float4*>(Bp + k0 + 4);
        } else {
            if ((k0 + b_k) < K) {
                const float* bp = Bp + (long)k0 * ldb;
                *reinterpret_cast<float4*>(vb)     = *reinterpret_cast<const float4*>(bp);
                *reinterpret_cast<float4*>(vb + 4) = *reinterpret_cast<const float4*>(bp + 4);
            } else {
                #pragma unroll
                for (int j = 0; j < 8; j++) vb[j] = 0.f;
            }
        }
    };

    auto sts = [&](int s) {
        #pragma unroll
        for (int j = 0; j < 8; j++) {
            int k = a_kg + j;
            int srow = ((k >> 3) << 2) + (k & 3);
            int comp = (((k >> 2) & 1) << 1) | a_half;
            (&As4[s][srow][a_idx].x)[comp] = RND ? totf(va[j]) : va[j];
        }
        if (BT) {
            #pragma unroll
            for (int j = 0; j < 8; j++) {
                int k = b_kg + j;
                int srow = ((k >> 3) << 2) + (k & 3);
                int comp = (bsel << 1) | ((k >> 2) & 1);
                (&Bs4[s][srow][bq].x)[comp] = RND ? totf(vb[j]) : vb[j];
            }
        } else {
            int srow = ((b_k >> 3) << 2) + (b_k & 3);
            int comp = (bsel << 1) | ((b_k >> 2) & 1);
            int p0 = (b_n8 >> 4) << 3;
            int x  = (p0 >> 3) & 7;
            #pragma unroll
            for (int j = 0; j < 8; j++) {
                int q = p0 + (j ^ x);
                (&Bs4[s][srow][q].x)[comp] = RND ? totf(vb[j]) : vb[j];
            }
        }
    };

    auto comp = [&](int s) {
        #pragma unroll
        for (int ks = 0; ks < 2; ks++) {
            float4 af[2], bf[4];
            #pragma unroll
            for (int mt = 0; mt < 2; mt++)
                af[mt] = As4[s][ks * 4 + tig][(wm * 2 + mt) * 8 + g];
            #pragma unroll
            for (int np = 0; np < 4; np++) {
                int j = wn * 32 + np * 8 + g;
                bf[np] = Bs4[s][ks * 4 + tig][j ^ ((j >> 3) & 7)];
            }
            #pragma unroll
            for (int mt = 0; mt < 2; mt++)
                #pragma unroll
                for (int np = 0; np < 4; np++) {
                    mma8(acc[mt][2 * np],
                         make_float2(af[mt].x, af[mt].y), make_float2(af[mt].z, af[mt].w),
                         make_float2(bf[np].x, bf[np].y));
                    mma8(acc[mt][2 * np + 1],
                         make_float2(af[mt].x, af[mt].y), make_float2(af[mt].z, af[mt].w),
                         make_float2(bf[np].z, bf[np].w));
                }
        }
    };

    ldg(0); sts(0); __syncthreads();
    for (int t = 0; t < T; t++) {
        if (t + 1 < T) ldg((t + 1) << 4);
        comp(t & 1);
        if (t + 1 < T) { sts((t + 1) & 1); __syncthreads(); }
    }

    // ---------------- epilogue ----------------
    #pragma unroll
    for (int mt = 0; mt < 2; mt++) {
        int mrow = m0 + wm * 32 + mt * 16 + g;
        #pragma unroll
        for (int half = 0; half < 2; half++) {
            int m = mrow + half * 8;
            if (GUARD && m >= M) continue;
            #pragma unroll
            for (int nt = 0; nt < 8; nt++) {
                int n = n0 + wn * 64 + nt * 8 + tig * 2;
                float bv0 = (n     < nsb) ? bias1[n]     : bias2[n - nsb];
                float bv1 = (n + 1 < nsb) ? bias1[n + 1] : bias2[n + 1 - nsb];
                float v0 = acc[mt][nt][half * 2 + 0] + bv0;
                float v1 = acc[mt][nt][half * 2 + 1] + bv1;
                float2* cp = reinterpret_cast<float2*>(C + (long)m * ldc + n);
                if (EPI == 1) {
                    float2 hv = *reinterpret_cast<const float2*>(A1 + (long)m * lda + n);
                    float2 dv = *reinterpret_cast<const float2*>(A2 + (long)m * lda + n);
                    float a0 = sigm(v0), a1 = sigm(v1);
                    *cp = make_float2(a0 * hv.x + (1.f - a0) * dv.x,
                                      a1 * hv.y + (1.f - a1) * dv.y);
                } else if (EPI == 2) {
                    *cp = make_float2(totf(v0), totf(v1));
                } else {
                    *cp = make_float2(v0, v1);
                }
            }
        }
    }
}

// ---------------- fused weight rounding + zero (single launch) ----------------
__global__ void wround_k(const float4* w_ih, const float4* w_hh,
                         const float4* W_ein, const float4* W_eout, const float4* W_hn,
                         float4* wih, float4* whh, float4* we, float4* whn,
                         float4* zero)
{
    const int S0 = 24576, S1 = S0 + 12288, S2 = S1 + 4096, S3 = S2 + 4096,
              S4 = S3 + 8192, S5 = S4 + 32;
    for (int i = blockIdx.x * blockDim.x + threadIdx.x; i < S5; i += gridDim.x * blockDim.x) {
        if (i >= S4) { zero[i - S4] = make_float4(0.f, 0.f, 0.f, 0.f); continue; }
        const float4* s; float4* d; int j;
        if      (i < S0) { s = w_ih;   d = wih;        j = i; }
        else if (i < S1) { s = w_hh;   d = whh;        j = i - S0; }
        else if (i < S2) { s = W_ein;  d = we;         j = i - S1; }
        else if (i < S3) { s = W_eout; d = we + 4096;  j = i - S2; }
        else             { s = W_hn;   d = whn;        j = i - S3; }
        float4 v = s[j];
        d[j] = make_float4(totf(v.x), totf(v.y), totf(v.z), totf(v.w));
    }
}

// ------- combined gi bias + q-vectors (one launch, 384 threads) -------
// bc[g]  = b_ih[g] + b_iah.w_ih[g,:128] + b_oah.w_ih[g,128:]
// qin[g] = b_ein.w_ih[g,:128] ; qout[g] = b_eout.w_ih[g,128:]
__global__ void bcq_k(const float* __restrict__ b_ih,
                      const float* __restrict__ b_iah, const float* __restrict__ b_oah,
                      const float* __restrict__ b_ein, const float* __restrict__ b_eout,
                      const float* __restrict__ w_ih_raw,
                      float* __restrict__ bc, float* __restrict__ qv)
{
    int gidx = blockIdx.x * blockDim.x + threadIdx.x;
    if (gidx >= 3 * HH) return;
    const float* wr = w_ih_raw + (long)gidx * 2 * HH;
    float s = b_ih[gidx], qi = 0.f, qo = 0.f;
    #pragma unroll 4
    for (int c = 0; c < HH; c++) {
        float w0 = wr[c], w1 = wr[HH + c];
        s  += b_iah[c] * w0 + b_oah[c] * w1;
        qi += b_ein[c] * w0;
        qo += b_eout[c] * w1;
    }
    bc[gidx] = s;
    qv[gidx] = qi;
    qv[3 * HH + gidx] = qo;
}

// ---------------- A rowsums: rs[m*2+hf] = sum_j A[m, hf*NN + j] ----------------
__global__ void rowsum_k(const float* __restrict__ A, float* __restrict__ rs)
{
    int idx = blockIdx.x * blockDim.x + threadIdx.x;
    if (idx >= MTOT * 2) return;
    long m = idx >> 1;
    int hf = idx & 1;
    const float4* ar = reinterpret_cast<const float4*>(A + m * (2 * NN) + hf * NN);
    float s = 0.f;
    #pragma unroll 5
    for (int j = 0; j < NN / 4; j++) {
        float4 v = ar[j];
        s += v.x + v.y + v.z + v.w;
    }
    rs[idx] = s;
}

// ---------------- wide gather (rounded) ----------------
__global__ void gather_k(const int* __restrict__ inputs,
                         const float4* __restrict__ emb4,
                         float4* __restrict__ h04, long total4)
{
    long i = (long)blockIdx.x * blockDim.x + threadIdx.x;
    if (i >= total4) return;
    long m = i >> 5;
    int  t = (int)(i & 31);
    float4 v = emb4[(long)inputs[m] * 32 + t];
    h04[i] = make_float4(totf(v.x), totf(v.y), totf(v.z), totf(v.w));
}

__global__ void pool_k(const float* __restrict__ h0,
                       const int* __restrict__ gm,
                       float* __restrict__ star)
{
    int b = blockIdx.x, t = threadIdx.x;
    const float* hb = h0 + (long)b * NN * HH;
    const int* gb = gm + b * NN;
    float s0 = 0.f, s1 = 0.f, s2 = 0.f, s3 = 0.f, c = 0.f;
    #pragma unroll 1
    for (int i = 0; i < NN; i += 4) {
        float g0 = (float)gb[i],     g1 = (float)gb[i + 1];
        float g2 = (float)gb[i + 2], g3 = (float)gb[i + 3];
        s0 += g0 * hb[(long)(i    ) * HH + t];
        s1 += g1 * hb[(long)(i + 1) * HH + t];
        s2 += g2 * hb[(long)(i + 2) * HH + t];
        s3 += g3 * hb[(long)(i + 3) * HH + t];
        c += g0 + g1 + g2 + g3;
    }
    star[b * HH + t] = (s0 + s1 + s2 + s3) / c;
}

// -------- wide GRU (float4) with b_e rowsum correction folded in --------
// gi_eff[m, g] = gi[m, g] + rs[m,0]*qin[g] + rs[m,1]*qout[g]
__global__ void gru_k(const float4* __restrict__ gi4, const float4* __restrict__ gh4,
                      const float4* __restrict__ h04,
                      const float* __restrict__ rs,
                      const float4* __restrict__ qv4,   // [qin(96) | qout(96)] float4
                      float4* __restrict__ hout4, long total4)
{
    long i = (long)blockIdx.x * blockDim.x + threadIdx.x;
    if (i >= total4) return;
    long m = i >> 5;
    int  j = (int)(i & 31);
    long base = m * 96;
    float ri = rs[m * 2], ro = rs[m * 2 + 1];

    float4 ir = gi4[base + j], ii = gi4[base + 32 + j], in_ = gi4[base + 64 + j];
    float4 hr = gh4[base + j], hi = gh4[base + 32 + j], hn  = gh4[base + 64 + j];
    float4 h  = h04[i];

    #pragma unroll
    for (int gate = 0; gate < 3; gate++) {
        float4 qi = qv4[gate * 32 + j];
        float4 qo = qv4[96 + gate * 32 + j];
        float4* t = (gate == 0) ? &ir : (gate == 1) ? &ii : &in_;
        t->x += ri * qi.x + ro * qo.x;
        t->y += ri * qi.y + ro * qo.y;
        t->z += ri * qi.z + ro * qo.z;
        t->w += ri * qi.w + ro * qo.w;
    }

    float4 o;
    { float r = sigm(ir.x + hr.x); float ig = sigm(ii.x + hi.x);
      float ng = tanhf(in_.x + r * hn.x); o.x = ng + ig * (h.x - ng); }
    { float r = sigm(ir.y + hr.y); float ig = sigm(ii.y + hi.y);
      float ng = tanhf(in_.y + r * hn.y); o.y = ng + ig * (h.y - ng); }
    { float r = sigm(ir.z + hr.z); float ig = sigm(ii.z + hi.z);
      float ng = tanhf(in_.z + r * hn.z); o.z = ng + ig * (h.z - ng); }
    { float r = sigm(ir.w + hr.w); float ig = sigm(ii.w + hi.w);
      float ng = tanhf(in_.w + r * hn.w); o.w = ng + ig * (h.w - ng); }
    hout4[i] = o;
}

// ---------------- star blend + attention pooling ----------------
__global__ void star_k(float* __restrict__ hidden,
                       const int* __restrict__ gm,
                       const float* __restrict__ star_in,
                       float* __restrict__ star_out)
{
    const float inv_sqrt_h = 0.0883883476483184f;
    int b = blockIdx.x;
    int t = threadIdx.x;
    int lane = t & 31, warp = t >> 5;

    __shared__ float st[HH];
    __shared__ float w[NN];
    __shared__ float red[HH];

    st[t] = star_in[(long)b * HH + t];
    __syncthreads();

    float ssp = 0.f;
    #pragma unroll
    for (int u = 0; u < 4; u++) { float v = st[lane + 32 * u]; ssp += v * v; }
    #pragma unroll
    for (int off = 16; off > 0; off >>= 1) ssp += __shfl_xor_sync(0xffffffffu, ssp, off);
    float ss = ssp;

    float* hb = hidden + (long)b * NN * HH;

    for (int i = warp; i < NN; i += 4) {
        float* hr = hb + (long)i * HH;
        float d = 0.f;
        #pragma unroll
        for (int u = 0; u < 4; u++) d += hr[lane + 32 * u] * st[lane + 32 * u];
        #pragma unroll
        for (int off = 16; off > 0; off >>= 1) d += __shfl_xor_sync(0xffffffffu, d, off);
        float alpha = sigm(d * inv_sqrt_h);
        #pragma unroll
        for (int u = 0; u < 4; u++) {
            int c = lane + 32 * u;
            hr[c] = totf((1.f - alpha) * hr[c] + alpha * st[c]);
        }
        float d2 = (1.f - alpha) * d + alpha * ss;
        if (lane == 0) w[i] = expf(d2) * (float)gm[b * NN + i];
    }
    __syncthreads();

    red[t] = (t < NN) ? w[t] : 0.f;
    __syncthreads();
    for (int s = 64; s > 0; s >>= 1) {
        if (t < s) red[t] += red[t + s];
        __syncthreads();
    }
    float S = red[0] + 1e-24f;

    float a0 = 0.f, a1 = 0.f, a2 = 0.f, a3 = 0.f;
    #pragma unroll 1
    for (int i = 0; i < NN; i += 4) {
        a0 += w[i]     * hb[(long)(i    ) * HH + t];
        a1 += w[i + 1] * hb[(long)(i + 1) * HH + t];
        a2 += w[i + 2] * hb[(long)(i + 2) * HH + t];
        a3 += w[i + 3] * hb[(long)(i + 3) * HH + t];
    }
    star_out[(long)b * HH + t] = (a0 + a1 + a2 + a3) / S;
}

// ---------------- launch ----------------
extern "C" void kernel_launch(void* const* d_in, const int* in_sizes, int n_in,
                              void* d_out, int out_size)
{
    const int*   inputs = (const int*)d_in[0];
    const float* A      = (const float*)d_in[1];
    const int*   gm     = (const int*)d_in[2];
    const float* emb    = (const float*)d_in[3];
    const float* w_ih   = (const float*)d_in[4];
    const float* w_hh   = (const float*)d_in[5];
    const float* b_ih   = (const float*)d_in[6];
    const float* b_hh   = (const float*)d_in[7];
    const float* b_iah  = (const float*)d_in[8];
    const float* b_oah  = (const float*)d_in[9];
    const float* W_ein  = (const float*)d_in[10];
    const float* b_ein  = (const float*)d_in[11];
    const float* W_eout = (const float*)d_in[12];
    const float* b_eout = (const float*)d_in[13];
    const float* W_hn   = (const float*)d_in[14];
    const float* b_hn   = (const float*)d_in[15];
    float* out = (float*)d_out;

    float *h0, *tmp, *gi, *gh, *hid, *star, *rs;
    float *wih, *whh, *we, *whn, *wc, *bc, *qv, *zero;
    cudaGetSymbolAddress((void**)&h0,   g_h0);
    cudaGetSymbolAddress((void**)&tmp,  g_tmp);
    cudaGetSymbolAddress((void**)&gi,   g_gi);
    cudaGetSymbolAddress((void**)&gh,   g_gh);
    cudaGetSymbolAddress((void**)&hid,  g_hid);
    cudaGetSymbolAddress((void**)&star, g_star);
    cudaGetSymbolAddress((void**)&rs,   g_rs);
    cudaGetSymbolAddress((void**)&wih,  g_wih);
    cudaGetSymbolAddress((void**)&whh,  g_whh);
    cudaGetSymbolAddress((void**)&we,   g_we);
    cudaGetSymbolAddress((void**)&whn,  g_whn);
    cudaGetSymbolAddress((void**)&wc,   g_wc);
    cudaGetSymbolAddress((void**)&bc,   g_bc);
    cudaGetSymbolAddress((void**)&qv,   g_qv);
    cudaGetSymbolAddress((void**)&zero, g_zero);

    const long totBNH = (long)MTOT * HH;
    const int BIG = 1 << 30;

    // 0) prep: round weights, combined bias + q-vectors, Wc = wih_z @ We_z
    wround_k<<<208, 256>>>((const float4*)w_ih, (const float4*)w_hh,
                           (const float4*)W_ein, (const float4*)W_eout, (const float4*)W_hn,
                           (float4*)wih, (float4*)whh, (float4*)we, (float4*)whn,
                           (float4*)zero);
    bcq_k<<<3, 128>>>(b_ih, b_iah, b_oah, b_ein, b_eout, w_ih, bc, qv);
    tc_gemm<false, false, 2, false, false, false><<<dim3(1, 3, 2), 256>>>(
        wih, wih, 128, 2 * HH, 0,
        we, we, BIG, (long)HH * HH, HH,
        zero, zero, BIG,
        wc, 128, 2 * HH,
        3 * HH, HH, HH);

    // 1) gather (rounded) + initial star + A rowsums
    gather_k<<<(unsigned)((totBNH / 4 + 255) / 256), 256>>>(
        inputs, (const float4*)emb, (float4*)h0, totBNH / 4);
    pool_k<<<BSZ, HH>>>(h0, gm, star);
    rowsum_k<<<(MTOT * 2 + 255) / 256, 256>>>(A, rs);

    // 2) adjacency: tmp = [A_in@h0 | A_out@h0]  (rounded store; B = shared h0 block)
    tc_gemm<false, true, 2, false, true, true><<<dim3(1, 1, 2 * BSZ), 256>>>(
        A, A, (long)NN * 2 * NN, 2 * NN, 0,
        h0, h0, BIG, (long)NN * HH, HH,
        zero, zero, BIG,
        tmp, (long)NN * 2 * HH, 2 * HH,
        NN, HH, NN);

    // 3) gi = tmp @ Wc^T + bc   (K=256; b_e correction applied in gru_k)
    tc_gemm<true, false, 0, false, false, false><<<dim3(3, MTOT / 128), 256>>>(
        tmp, tmp, 0, 2 * HH, 0,
        wc, wc, BIG, 0, 2 * HH,
        bc, bc, BIG,
        gi, 0, 3 * HH,
        MTOT, 3 * HH, 2 * HH);

    // 4) gh = h0 @ w_hh^T + b_hh
    tc_gemm<true, false, 0, false, false, false><<<dim3(3, MTOT / 128), 256>>>(
        h0, h0, 0, HH, 0,
        whh, whh, BIG, 0, HH,
        b_hh, b_hh, BIG,
        gh, 0, 3 * HH,
        MTOT, 3 * HH, HH);

    // 5) GRU (with rowsum*q correction) -> hid
    gru_k<<<(unsigned)((totBNH / 4 + 255) / 256), 256>>>(
        (const float4*)gi, (const float4*)gh, (const float4*)h0,
        rs, (const float4*)qv, (float4*)hid, totBNH / 4);

    // 6) star blend + attention pooling
    star_k<<<BSZ, HH>>>(hid, gm, star, out + totBNH);

    // 7) highway fused: [h0|hid] @ W_hn^T + b_hn (split-K), sigmoid blend -> out
    tc_gemm<true, false, 1, true, false, false><<<dim3(1, MTOT / 128), 256>>>(
        h0, hid, 0, HH, HH,
        whn, whn, BIG, 0, 2 * HH,
        b_hn, b_hn, BIG,
        out, 0, HH,
        MTOT, HH, 2 * HH);
}